// round 4
// baseline (speedup 1.0000x reference)
#include <cuda_runtime.h>
#include <math.h>

#define Bdim 256
#define Jdim 64
#define Ddim 512
#define SROWSTRIDE 36   // padded stride for transposed s tile (16B aligned, conflict-free)

// Scratch (allocation-free rule: __device__ globals)
__device__ float g_Q[Bdim * Ddim];    // inputs @ W
__device__ float g_P[Jdim * Ddim];    // keys @ V + U_bias
__device__ float g_G0[Bdim * Jdim];   // inputs @ keys^T

// ---------------- cp.async helpers ----------------
__device__ __forceinline__ void cp_async16(void* smem_dst, const void* gmem_src) {
    unsigned s = (unsigned)__cvta_generic_to_shared(smem_dst);
    asm volatile("cp.async.cg.shared.global [%0], [%1], 16;\n" :: "r"(s), "l"(gmem_src));
}
__device__ __forceinline__ void cp_commit() { asm volatile("cp.async.commit_group;\n"); }
__device__ __forceinline__ void cp_wait1()  { asm volatile("cp.async.wait_group 1;\n"); }
__device__ __forceinline__ void cp_wait0()  { asm volatile("cp.async.wait_group 0;\n"); }

// ---------------- small precompute SGEMM: C[M,N] = A[M,K] @ Bm[K,N] (+bias) ----------------
// 64x64 tile, BK=16, 256 threads, 4x4 per-thread micro tile. M,N multiples of 64, K mult of 16.
__global__ __launch_bounds__(256) void sgemm_tile64(
    const float* __restrict__ A, const float* __restrict__ Bm,
    const float* __restrict__ bias, float* __restrict__ C,
    int M, int N, int K)
{
    __shared__ float As[16][64];   // transposed A tile: As[k][m]
    __shared__ float Bs[16][64];
    int tid = threadIdx.x;
    int n0 = blockIdx.x * 64;
    int m0 = blockIdx.y * 64;
    int ty = tid >> 4, tx = tid & 15;
    float acc[4][4];
#pragma unroll
    for (int i = 0; i < 4; i++)
#pragma unroll
        for (int j = 0; j < 4; j++) acc[i][j] = 0.f;

    for (int k0 = 0; k0 < K; k0 += 16) {
        {   // A tile: 64x16 floats, each thread one float4 along K
            int m  = tid >> 2;
            int kk = (tid & 3) * 4;
            float4 v = *reinterpret_cast<const float4*>(&A[(size_t)(m0 + m) * K + k0 + kk]);
            As[kk + 0][m] = v.x; As[kk + 1][m] = v.y;
            As[kk + 2][m] = v.z; As[kk + 3][m] = v.w;
        }
        {   // B tile: 16x64 floats
            int kk = tid >> 4;
            int c4 = (tid & 15) * 4;
            *reinterpret_cast<float4*>(&Bs[kk][c4]) =
                *reinterpret_cast<const float4*>(&Bm[(size_t)(k0 + kk) * N + n0 + c4]);
        }
        __syncthreads();
#pragma unroll
        for (int kk = 0; kk < 16; kk++) {
            float4 a4 = *reinterpret_cast<const float4*>(&As[kk][ty * 4]);
            float4 b4 = *reinterpret_cast<const float4*>(&Bs[kk][tx * 4]);
            float a[4] = {a4.x, a4.y, a4.z, a4.w};
            float b[4] = {b4.x, b4.y, b4.z, b4.w};
#pragma unroll
            for (int i = 0; i < 4; i++)
#pragma unroll
                for (int j = 0; j < 4; j++) acc[i][j] += a[i] * b[j];
        }
        __syncthreads();
    }
    float bx = 0.f, by = 0.f, bz = 0.f, bw = 0.f;
    if (bias) {
        bx = bias[n0 + tx * 4 + 0]; by = bias[n0 + tx * 4 + 1];
        bz = bias[n0 + tx * 4 + 2]; bw = bias[n0 + tx * 4 + 3];
    }
#pragma unroll
    for (int i = 0; i < 4; i++) {
        float4 o;
        o.x = acc[i][0] + bx; o.y = acc[i][1] + by;
        o.z = acc[i][2] + bz; o.w = acc[i][3] + bw;
        *reinterpret_cast<float4*>(&C[(size_t)(m0 + ty * 4 + i) * N + n0 + tx * 4]) = o;
    }
}

// ---------------- G0[b,j] = dot(inputs[b], keys[j]) ----------------
__global__ __launch_bounds__(256) void gate_keys_kernel(
    const float* __restrict__ inputs, const float* __restrict__ keys)
{
    __shared__ float inp[Ddim];
    int b = blockIdx.x, tid = threadIdx.x;
    if (tid < 128)
        reinterpret_cast<float4*>(inp)[tid] =
            reinterpret_cast<const float4*>(inputs + (size_t)b * Ddim)[tid];
    __syncthreads();
    int w = tid >> 5, lane = tid & 31;
    for (int j = w; j < Jdim; j += 8) {
        const float* kr = keys + (size_t)j * Ddim;
        float z = 0.f;
        for (int k = lane; k < Ddim; k += 32) z += inp[k] * kr[k];
#pragma unroll
        for (int o = 16; o; o >>= 1) z += __shfl_xor_sync(0xffffffffu, z, o);
        if (lane == 0) g_G0[b * Jdim + j] = z;
    }
}

// ---------------- fused main kernel ----------------
// One CTA = 32 consecutive rows of the [16384, 512] state matrix (one b, 32 j's).
// Computes  v = s + sigmoid(inputs.s + G0) * relu(s@U + Q[b] + P[j]),
// then out = (v > 0) ? ||v_row|| : v.
__global__ __launch_bounds__(256, 2) void fused_kernel(
    const float* __restrict__ inputs,
    const float* __restrict__ state,
    const float* __restrict__ U,
    float* __restrict__ out)
{
    extern __shared__ float sm[];
    float* sT    = sm;                           // [512][36] transposed s tile
    float* Ubuf  = sm + Ddim * SROWSTRIDE;       // 2 x [8][512] U tiles (double buffer)
    float* inp   = Ubuf + 2 * 8 * Ddim;          // [512] inputs[b]
    float* qb    = inp + Ddim;                   // [512] Q[b]
    float* gate  = qb + Ddim;                    // [32]
    float* normv = gate + 32;                    // [32]
    float* red   = normv + 32;                   // [8][32] norm partials

    int tid  = threadIdx.x;
    int bx   = blockIdx.x;
    int row0 = bx * 32;
    int b    = bx >> 1;
    int j0   = (bx & 1) * 32;
    const float* srow = state + (size_t)row0 * Ddim;

    // Prefetch U k-tiles 0 and 1 (each 8x512 floats) via cp.async
#pragma unroll
    for (int q = 0; q < 4; q++) {
        int c = tid + 256 * q;
        int kk = c >> 7, c4 = (c & 127) * 4;
        cp_async16(Ubuf + kk * Ddim + c4, U + (size_t)kk * Ddim + c4);
    }
    cp_commit();
#pragma unroll
    for (int q = 0; q < 4; q++) {
        int c = tid + 256 * q;
        int kk = c >> 7, c4 = (c & 127) * 4;
        cp_async16(Ubuf + 4096 + kk * Ddim + c4, U + (size_t)(8 + kk) * Ddim + c4);
    }
    cp_commit();

    // Stage inputs[b] and Q[b]
    if (tid < 128)
        reinterpret_cast<float4*>(inp)[tid] =
            reinterpret_cast<const float4*>(inputs + (size_t)b * Ddim)[tid];
    else
        reinterpret_cast<float4*>(qb)[tid - 128] =
            reinterpret_cast<const float4*>(g_Q + (size_t)b * Ddim)[tid - 128];

    // Stage s block, transposed: sT[k][row]
#pragma unroll
    for (int q = 0; q < 16; q++) {
        int c = tid + 256 * q;
        int r = c >> 7;
        int f4 = c & 127;
        float4 v = reinterpret_cast<const float4*>(srow + (size_t)r * Ddim)[f4];
        int cb = f4 * 4;
        sT[(cb + 0) * SROWSTRIDE + r] = v.x;
        sT[(cb + 1) * SROWSTRIDE + r] = v.y;
        sT[(cb + 2) * SROWSTRIDE + r] = v.z;
        sT[(cb + 3) * SROWSTRIDE + r] = v.w;
    }
    __syncthreads();

    // Gates: warp w handles rows w*4..w*4+3
    {
        int w = tid >> 5, lane = tid & 31;
#pragma unroll
        for (int i = 0; i < 4; i++) {
            int r = w * 4 + i;
            float z = 0.f;
            for (int k = lane; k < Ddim; k += 32) z += inp[k] * sT[k * SROWSTRIDE + r];
#pragma unroll
            for (int o = 16; o; o >>= 1) z += __shfl_xor_sync(0xffffffffu, z, o);
            if (lane == 0) {
                float zz = z + g_G0[b * Jdim + j0 + r];
                gate[r] = 1.f / (1.f + expf(-zz));
            }
        }
    }

    // GEMM mainloop: acc[4 rows][16 cols] per thread
    int rg = tid & 7;           // row group (rows rg*4..rg*4+3)
    int cg = tid >> 3;          // col group (cols cg*16..cg*16+15)
    int colbase = cg * 16;

    float acc[4][16];
#pragma unroll
    for (int i = 0; i < 4; i++)
#pragma unroll
        for (int u = 0; u < 16; u++) acc[i][u] = 0.f;

#pragma unroll 1
    for (int s = 0; s < 64; s++) {
        if (s < 62) cp_wait1(); else cp_wait0();
        __syncthreads();
        const float* Ub = Ubuf + (s & 1) * 4096;
#pragma unroll
        for (int kk = 0; kk < 8; kk++) {
            float4 a4 = *reinterpret_cast<const float4*>(&sT[(s * 8 + kk) * SROWSTRIDE + rg * 4]);
            float a[4] = {a4.x, a4.y, a4.z, a4.w};
            const float4* br = reinterpret_cast<const float4*>(Ub + kk * Ddim + colbase);
            float4 b0 = br[0], b1 = br[1], b2 = br[2], b3 = br[3];
            float bb[16] = {b0.x, b0.y, b0.z, b0.w, b1.x, b1.y, b1.z, b1.w,
                            b2.x, b2.y, b2.z, b2.w, b3.x, b3.y, b3.z, b3.w};
#pragma unroll
            for (int i = 0; i < 4; i++)
#pragma unroll
                for (int u = 0; u < 16; u++) acc[i][u] += a[i] * bb[u];
        }
        __syncthreads();
        if (s + 2 < 64) {
            const float* Ug = U + (size_t)(s + 2) * 8 * Ddim;
            float* Ud = Ubuf + (s & 1) * 4096;
#pragma unroll
            for (int q = 0; q < 4; q++) {
                int c = tid + 256 * q;
                int kk = c >> 7, c4 = (c & 127) * 4;
                cp_async16(Ud + kk * Ddim + c4, Ug + (size_t)kk * Ddim + c4);
            }
            cp_commit();
        }
    }

    // Epilogue: s_next values + row-norm partials
    float part[4] = {0.f, 0.f, 0.f, 0.f};
#pragma unroll
    for (int i = 0; i < 4; i++) {
        int row = rg * 4 + i;
        float g = gate[row];
        const float* Pr = g_P + (size_t)(j0 + row) * Ddim + colbase;
#pragma unroll
        for (int u4 = 0; u4 < 4; u4++) {
            float4 p4 = reinterpret_cast<const float4*>(Pr)[u4];
            float pv[4] = {p4.x, p4.y, p4.z, p4.w};
#pragma unroll
            for (int j = 0; j < 4; j++) {
                int u = u4 * 4 + j;
                float pre = acc[i][u] + qb[colbase + u] + pv[j];
                float c = pre > 0.f ? pre : 0.f;               // relu
                float v = sT[(colbase + u) * SROWSTRIDE + row] + g * c;
                acc[i][u] = v;
                part[i] += v * v;
            }
        }
    }
    // Deterministic reduction: 4 cg-locals per warp via shfl, then 8 warps via smem
#pragma unroll
    for (int i = 0; i < 4; i++) {
        part[i] += __shfl_xor_sync(0xffffffffu, part[i], 8);
        part[i] += __shfl_xor_sync(0xffffffffu, part[i], 16);
    }
    {
        int w = tid >> 5;
        if (((tid >> 3) & 3) == 0) {   // lanes 0..7 of each warp hold the warp's row sums
#pragma unroll
            for (int i = 0; i < 4; i++) red[w * 32 + rg * 4 + i] = part[i];
        }
    }
    __syncthreads();
    if (tid < 32) {
        float sum = 0.f;
#pragma unroll
        for (int w = 0; w < 8; w++) sum += red[w * 32 + tid];
        normv[tid] = fmaxf(sqrtf(sum), 1e-12f);
    }
    __syncthreads();

    // out = (v > 0) ? norm : v
#pragma unroll
    for (int i = 0; i < 4; i++) {
        int row = rg * 4 + i;
        float n = normv[row];
        float* orow = out + (size_t)(row0 + row) * Ddim + colbase;
#pragma unroll
        for (int u4 = 0; u4 < 4; u4++) {
            float4 o;
            o.x = acc[i][u4 * 4 + 0] > 0.f ? n : acc[i][u4 * 4 + 0];
            o.y = acc[i][u4 * 4 + 1] > 0.f ? n : acc[i][u4 * 4 + 1];
            o.z = acc[i][u4 * 4 + 2] > 0.f ? n : acc[i][u4 * 4 + 2];
            o.w = acc[i][u4 * 4 + 3] > 0.f ? n : acc[i][u4 * 4 + 3];
            reinterpret_cast<float4*>(orow)[u4] = o;
        }
    }
}

extern "C" void kernel_launch(void* const* d_in, const int* in_sizes, int n_in,
                              void* d_out, int out_size)
{
    const float* inputs = (const float*)d_in[0];
    const float* state  = (const float*)d_in[1];
    const float* keys   = (const float*)d_in[2];
    const float* U      = (const float*)d_in[3];
    const float* V      = (const float*)d_in[4];
    const float* W      = (const float*)d_in[5];
    const float* Ubias  = (const float*)d_in[6];
    float* out = (float*)d_out;
    (void)in_sizes; (void)n_in; (void)out_size;

    void *pQ = nullptr, *pP = nullptr;
    cudaGetSymbolAddress(&pQ, g_Q);
    cudaGetSymbolAddress(&pP, g_P);

    // Q = inputs @ W            [256, 512]
    sgemm_tile64<<<dim3(Ddim / 64, Bdim / 64), 256>>>(inputs, W, nullptr, (float*)pQ, Bdim, Ddim, Ddim);
    // P = keys @ V + U_bias     [64, 512]
    sgemm_tile64<<<dim3(Ddim / 64, Jdim / 64), 256>>>(keys, V, Ubias, (float*)pP, Jdim, Ddim, Ddim);
    // G0 = inputs @ keys^T      [256, 64]
    gate_keys_kernel<<<Bdim, 256>>>(inputs, keys);

    size_t smem = (size_t)(Ddim * SROWSTRIDE + 2 * 8 * Ddim + Ddim + Ddim + 32 + 32 + 8 * 32) * sizeof(float);
    cudaFuncSetAttribute(fused_kernel, cudaFuncAttributeMaxDynamicSharedMemorySize, (int)smem);
    fused_kernel<<<(Bdim * Jdim) / 32, 256, smem>>>(inputs, state, U, out);
}

// round 5
// speedup vs baseline: 1.1273x; 1.1273x over previous
#include <cuda_runtime.h>
#include <math.h>

#define Bdim 256
#define Jdim 64
#define Ddim 512
#define SROWSTRIDE 36   // padded stride for transposed s tile (16B aligned, conflict-free)

// Scratch (allocation-free rule: __device__ globals)
__device__ float g_Q[Bdim * Ddim];    // inputs @ W
__device__ float g_P[Jdim * Ddim];    // keys @ V + U_bias

// ---------------- cp.async helpers ----------------
__device__ __forceinline__ void cp_async16(void* smem_dst, const void* gmem_src) {
    unsigned s = (unsigned)__cvta_generic_to_shared(smem_dst);
    asm volatile("cp.async.cg.shared.global [%0], [%1], 16;\n" :: "r"(s), "l"(gmem_src));
}
__device__ __forceinline__ void cp_commit() { asm volatile("cp.async.commit_group;\n"); }
__device__ __forceinline__ void cp_wait1()  { asm volatile("cp.async.wait_group 1;\n"); }
__device__ __forceinline__ void cp_wait0()  { asm volatile("cp.async.wait_group 0;\n"); }

// ---------------- packed f32x2 helpers ----------------
__device__ __forceinline__ unsigned long long pack_dup(float a) {
    unsigned long long r;
    asm("mov.b64 %0, {%1, %1};" : "=l"(r) : "f"(a));
    return r;
}
__device__ __forceinline__ void ffma2(unsigned long long& d,
                                      unsigned long long a,
                                      unsigned long long b) {
    asm("fma.rn.f32x2 %0, %1, %2, %0;" : "+l"(d) : "l"(a), "l"(b));
}
__device__ __forceinline__ void unpack2(float& lo, float& hi, unsigned long long v) {
    asm("mov.b64 {%0, %1}, %2;" : "=f"(lo), "=f"(hi) : "l"(v));
}

// ---------------- combined precompute: Q = inputs@W ; P = keys@V + bias ----------------
// 64x64 tile SGEMM, BK=16, 256 threads, 4x4 micro tile. One launch, 40 CTAs.
__device__ __forceinline__ void sgemm_tile_body(
    const float* __restrict__ A, const float* __restrict__ Bm,
    const float* __restrict__ bias, float* __restrict__ C,
    int m0, int n0, int N, int K,
    float (*As)[64], float (*Bs)[64])
{
    int tid = threadIdx.x;
    int ty = tid >> 4, tx = tid & 15;
    float acc[4][4];
#pragma unroll
    for (int i = 0; i < 4; i++)
#pragma unroll
        for (int j = 0; j < 4; j++) acc[i][j] = 0.f;

    for (int k0 = 0; k0 < K; k0 += 16) {
        {   // A tile 64x16, transposed into As[k][m]
            int m  = tid >> 2;
            int kk = (tid & 3) * 4;
            float4 v = *reinterpret_cast<const float4*>(&A[(size_t)(m0 + m) * K + k0 + kk]);
            As[kk + 0][m] = v.x; As[kk + 1][m] = v.y;
            As[kk + 2][m] = v.z; As[kk + 3][m] = v.w;
        }
        {   // B tile 16x64
            int kk = tid >> 4;
            int c4 = (tid & 15) * 4;
            *reinterpret_cast<float4*>(&Bs[kk][c4]) =
                *reinterpret_cast<const float4*>(&Bm[(size_t)(k0 + kk) * N + n0 + c4]);
        }
        __syncthreads();
#pragma unroll
        for (int kk = 0; kk < 16; kk++) {
            float4 a4 = *reinterpret_cast<const float4*>(&As[kk][ty * 4]);
            float4 b4 = *reinterpret_cast<const float4*>(&Bs[kk][tx * 4]);
            float a[4] = {a4.x, a4.y, a4.z, a4.w};
            float b[4] = {b4.x, b4.y, b4.z, b4.w};
#pragma unroll
            for (int i = 0; i < 4; i++)
#pragma unroll
                for (int j = 0; j < 4; j++) acc[i][j] += a[i] * b[j];
        }
        __syncthreads();
    }
    float bx = 0.f, by = 0.f, bz = 0.f, bw = 0.f;
    if (bias) {
        bx = bias[n0 + tx * 4 + 0]; by = bias[n0 + tx * 4 + 1];
        bz = bias[n0 + tx * 4 + 2]; bw = bias[n0 + tx * 4 + 3];
    }
#pragma unroll
    for (int i = 0; i < 4; i++) {
        float4 o;
        o.x = acc[i][0] + bx; o.y = acc[i][1] + by;
        o.z = acc[i][2] + bz; o.w = acc[i][3] + bw;
        *reinterpret_cast<float4*>(&C[(size_t)(m0 + ty * 4 + i) * N + n0 + tx * 4]) = o;
    }
}

__global__ __launch_bounds__(256) void precompute_kernel(
    const float* __restrict__ inputs, const float* __restrict__ keys,
    const float* __restrict__ V, const float* __restrict__ W,
    const float* __restrict__ Ubias)
{
    __shared__ float As[16][64];
    __shared__ float Bs[16][64];
    int bx = blockIdx.x;
    if (bx < 32) {
        // Q = inputs @ W : tiles (m0 = (bx>>3)*64, n0 = (bx&7)*64)
        sgemm_tile_body(inputs, W, nullptr, g_Q,
                        (bx >> 3) * 64, (bx & 7) * 64, Ddim, Ddim, As, Bs);
    } else {
        // P = keys @ V + bias : 8 n-tiles, single m-tile (J=64)
        int t = bx - 32;
        sgemm_tile_body(keys, V, Ubias, g_P,
                        0, t * 64, Ddim, Ddim, As, Bs);
    }
}

// ---------------- fused main kernel ----------------
// One CTA = 32 consecutive rows of the [16384, 512] state matrix (one b, 32 j's).
// v = s + sigmoid(inputs.(s+key)) * relu(s@U + Q[b] + P[j]); out = (v>0) ? ||v_row|| : v.
__global__ __launch_bounds__(256, 2) void fused_kernel(
    const float* __restrict__ inputs,
    const float* __restrict__ state,
    const float* __restrict__ keys,
    const float* __restrict__ U,
    float* __restrict__ out)
{
    extern __shared__ float sm[];
    float* sT    = sm;                           // [512][36] transposed s tile
    float* Ubuf  = sm + Ddim * SROWSTRIDE;       // 2 x [8][512] U tiles (double buffer)
    float* inp   = Ubuf + 2 * 8 * Ddim;          // [512] inputs[b]
    float* qb    = inp + Ddim;                   // [512] Q[b]
    float* gate  = qb + Ddim;                    // [32]
    float* normv = gate + 32;                    // [32]
    float* red   = normv + 32;                   // [8][32] norm partials

    int tid  = threadIdx.x;
    int bx   = blockIdx.x;
    int row0 = bx * 32;
    int b    = bx >> 1;
    int j0   = (bx & 1) * 32;
    const float* srow = state + (size_t)row0 * Ddim;

    // Prefetch U k-tiles 0 and 1 (each 8x512 floats) via cp.async
#pragma unroll
    for (int q = 0; q < 4; q++) {
        int c = tid + 256 * q;
        int kk = c >> 7, c4 = (c & 127) * 4;
        cp_async16(Ubuf + kk * Ddim + c4, U + (size_t)kk * Ddim + c4);
    }
    cp_commit();
#pragma unroll
    for (int q = 0; q < 4; q++) {
        int c = tid + 256 * q;
        int kk = c >> 7, c4 = (c & 127) * 4;
        cp_async16(Ubuf + 4096 + kk * Ddim + c4, U + (size_t)(8 + kk) * Ddim + c4);
    }
    cp_commit();

    // Stage inputs[b] and Q[b]
    if (tid < 128)
        reinterpret_cast<float4*>(inp)[tid] =
            reinterpret_cast<const float4*>(inputs + (size_t)b * Ddim)[tid];
    else
        reinterpret_cast<float4*>(qb)[tid - 128] =
            reinterpret_cast<const float4*>(g_Q + (size_t)b * Ddim)[tid - 128];

    // Stage s block, transposed: sT[k][row]
#pragma unroll
    for (int q = 0; q < 16; q++) {
        int c = tid + 256 * q;
        int r = c >> 7;
        int f4 = c & 127;
        float4 v = reinterpret_cast<const float4*>(srow + (size_t)r * Ddim)[f4];
        int cb = f4 * 4;
        sT[(cb + 0) * SROWSTRIDE + r] = v.x;
        sT[(cb + 1) * SROWSTRIDE + r] = v.y;
        sT[(cb + 2) * SROWSTRIDE + r] = v.z;
        sT[(cb + 3) * SROWSTRIDE + r] = v.w;
    }
    __syncthreads();

    // Gates: warp w handles rows w*4..w*4+3.
    // gate arg = inputs.(s_j + key_j)  (folds the former inputs@keys^T kernel in)
    {
        int w = tid >> 5, lane = tid & 31;
#pragma unroll
        for (int i = 0; i < 4; i++) {
            int r = w * 4 + i;
            const float* kr = keys + (size_t)(j0 + r) * Ddim;
            float z = 0.f;
            for (int k = lane; k < Ddim; k += 32)
                z += inp[k] * (sT[k * SROWSTRIDE + r] + kr[k]);
#pragma unroll
            for (int o = 16; o; o >>= 1) z += __shfl_xor_sync(0xffffffffu, z, o);
            if (lane == 0) gate[r] = 1.f / (1.f + expf(-z));
        }
    }

    // GEMM mainloop: packed f32x2, acc[4 rows][8 col-pairs] per thread (4x16 scalar tile)
    int rg = tid & 7;           // row group (rows rg*4..rg*4+3)
    int cg = tid >> 3;          // col group (cols cg*16..cg*16+15)
    int colbase = cg * 16;

    unsigned long long acc[4][8];
#pragma unroll
    for (int i = 0; i < 4; i++)
#pragma unroll
        for (int u = 0; u < 8; u++) acc[i][u] = 0ull;

#pragma unroll 1
    for (int s = 0; s < 64; s++) {
        if (s < 62) cp_wait1(); else cp_wait0();
        __syncthreads();
        const float* Ub = Ubuf + (s & 1) * 4096;
#pragma unroll
        for (int kk = 0; kk < 8; kk++) {
            float4 a4 = *reinterpret_cast<const float4*>(&sT[(s * 8 + kk) * SROWSTRIDE + rg * 4]);
            unsigned long long ap[4];
            ap[0] = pack_dup(a4.x); ap[1] = pack_dup(a4.y);
            ap[2] = pack_dup(a4.z); ap[3] = pack_dup(a4.w);
            const ulonglong2* br = reinterpret_cast<const ulonglong2*>(Ub + kk * Ddim + colbase);
            ulonglong2 q0 = br[0], q1 = br[1], q2 = br[2], q3 = br[3];
            unsigned long long bq[8] = {q0.x, q0.y, q1.x, q1.y, q2.x, q2.y, q3.x, q3.y};
#pragma unroll
            for (int i = 0; i < 4; i++)
#pragma unroll
                for (int u = 0; u < 8; u++) ffma2(acc[i][u], ap[i], bq[u]);
        }
        __syncthreads();
        if (s + 2 < 64) {
            const float* Ug = U + (size_t)(s + 2) * 8 * Ddim;
            float* Ud = Ubuf + (s & 1) * 4096;
#pragma unroll
            for (int q = 0; q < 4; q++) {
                int c = tid + 256 * q;
                int kk = c >> 7, c4 = (c & 127) * 4;
                cp_async16(Ud + kk * Ddim + c4, Ug + (size_t)kk * Ddim + c4);
            }
            cp_commit();
        }
    }

    // Epilogue: s_next values + row-norm partials
    float vout[4][16];
    float part[4] = {0.f, 0.f, 0.f, 0.f};
#pragma unroll
    for (int i = 0; i < 4; i++) {
        int row = rg * 4 + i;
        float g = gate[row];
        const float* Pr = g_P + (size_t)(j0 + row) * Ddim + colbase;
#pragma unroll
        for (int u4 = 0; u4 < 4; u4++) {
            float4 p4 = reinterpret_cast<const float4*>(Pr)[u4];
            float pv[4] = {p4.x, p4.y, p4.z, p4.w};
            float av[4];
            unpack2(av[0], av[1], acc[i][u4 * 2 + 0]);
            unpack2(av[2], av[3], acc[i][u4 * 2 + 1]);
#pragma unroll
            for (int j = 0; j < 4; j++) {
                int u = u4 * 4 + j;
                float pre = av[j] + qb[colbase + u] + pv[j];
                float c = pre > 0.f ? pre : 0.f;               // relu
                float v = sT[(colbase + u) * SROWSTRIDE + row] + g * c;
                vout[i][u] = v;
                part[i] += v * v;
            }
        }
    }
    // Deterministic reduction: 4 cg-locals per warp via shfl, then 8 warps via smem
#pragma unroll
    for (int i = 0; i < 4; i++) {
        part[i] += __shfl_xor_sync(0xffffffffu, part[i], 8);
        part[i] += __shfl_xor_sync(0xffffffffu, part[i], 16);
    }
    {
        int w = tid >> 5;
        if (((tid >> 3) & 3) == 0) {   // lanes 0..7 of each warp hold the warp's row sums
#pragma unroll
            for (int i = 0; i < 4; i++) red[w * 32 + rg * 4 + i] = part[i];
        }
    }
    __syncthreads();
    if (tid < 32) {
        float sum = 0.f;
#pragma unroll
        for (int w = 0; w < 8; w++) sum += red[w * 32 + tid];
        normv[tid] = fmaxf(sqrtf(sum), 1e-12f);
    }
    __syncthreads();

    // out = (v > 0) ? norm : v
#pragma unroll
    for (int i = 0; i < 4; i++) {
        int row = rg * 4 + i;
        float n = normv[row];
        float* orow = out + (size_t)(row0 + row) * Ddim + colbase;
#pragma unroll
        for (int u4 = 0; u4 < 4; u4++) {
            float4 o;
            o.x = vout[i][u4 * 4 + 0] > 0.f ? n : vout[i][u4 * 4 + 0];
            o.y = vout[i][u4 * 4 + 1] > 0.f ? n : vout[i][u4 * 4 + 1];
            o.z = vout[i][u4 * 4 + 2] > 0.f ? n : vout[i][u4 * 4 + 2];
            o.w = vout[i][u4 * 4 + 3] > 0.f ? n : vout[i][u4 * 4 + 3];
            reinterpret_cast<float4*>(orow)[u4] = o;
        }
    }
}

extern "C" void kernel_launch(void* const* d_in, const int* in_sizes, int n_in,
                              void* d_out, int out_size)
{
    const float* inputs = (const float*)d_in[0];
    const float* state  = (const float*)d_in[1];
    const float* keys   = (const float*)d_in[2];
    const float* U      = (const float*)d_in[3];
    const float* V      = (const float*)d_in[4];
    const float* W      = (const float*)d_in[5];
    const float* Ubias  = (const float*)d_in[6];
    float* out = (float*)d_out;
    (void)in_sizes; (void)n_in; (void)out_size;

    // One launch: Q = inputs@W (32 tiles) and P = keys@V + bias (8 tiles), concurrent
    precompute_kernel<<<40, 256>>>(inputs, keys, V, W, Ubias);

    size_t smem = (size_t)(Ddim * SROWSTRIDE + 2 * 8 * Ddim + Ddim + Ddim + 32 + 32 + 8 * 32) * sizeof(float);
    cudaFuncSetAttribute(fused_kernel, cudaFuncAttributeMaxDynamicSharedMemorySize, (int)smem);
    fused_kernel<<<(Bdim * Jdim) / 32, 256, smem>>>(inputs, state, keys, U, out);
}

// round 6
// speedup vs baseline: 1.3410x; 1.1895x over previous
#include <cuda_runtime.h>
#include <math.h>

#define Bdim 256
#define Jdim 64
#define Ddim 512
#define SSTRIDE 520   // padded row stride (floats) for s tile  (2080B, 16B-aligned)
#define USTRIDE 520   // padded row stride (floats) for U k-slab

// Scratch (allocation-free rule: __device__ globals)
__device__ float g_Q[Bdim * Ddim];    // inputs @ W
__device__ float g_P[Jdim * Ddim];    // keys @ V + U_bias

// ---------------- cp.async helpers ----------------
__device__ __forceinline__ void cp_async16(void* smem_dst, const void* gmem_src) {
    unsigned s = (unsigned)__cvta_generic_to_shared(smem_dst);
    asm volatile("cp.async.cg.shared.global [%0], [%1], 16;\n" :: "r"(s), "l"(gmem_src));
}
__device__ __forceinline__ void cp_commit() { asm volatile("cp.async.commit_group;\n"); }
__device__ __forceinline__ void cp_wait1()  { asm volatile("cp.async.wait_group 1;\n"); }
__device__ __forceinline__ void cp_wait0()  { asm volatile("cp.async.wait_group 0;\n"); }

// ---------------- tf32 helpers ----------------
__device__ __forceinline__ unsigned f2tf32(float x) {
    unsigned r;
    asm("cvt.rna.tf32.f32 %0, %1;" : "=r"(r) : "f"(x));
    return r;
}
__device__ __forceinline__ void split_tf32(float x, unsigned& hi, unsigned& lo) {
    hi = f2tf32(x);
    float h = __uint_as_float(hi);
    lo = f2tf32(x - h);          // x - h exact in fp32, then round residual to tf32
}
// D += A(16x8,row) * B(8x8,col)   (tf32 inputs, fp32 accumulate)
__device__ __forceinline__ void mma_tf32(float d[4], const unsigned a[4], const unsigned b[2]) {
    asm volatile("mma.sync.aligned.m16n8k8.row.col.f32.tf32.tf32.f32 "
        "{%0,%1,%2,%3}, {%4,%5,%6,%7}, {%8,%9}, {%0,%1,%2,%3};"
        : "+f"(d[0]), "+f"(d[1]), "+f"(d[2]), "+f"(d[3])
        : "r"(a[0]), "r"(a[1]), "r"(a[2]), "r"(a[3]), "r"(b[0]), "r"(b[1]));
}

// ---------------- combined precompute: Q = inputs@W ; P = keys@V + bias ----------------
__device__ __forceinline__ void sgemm_tile_body(
    const float* __restrict__ A, const float* __restrict__ Bm,
    const float* __restrict__ bias, float* __restrict__ C,
    int m0, int n0, int N, int K,
    float (*As)[64], float (*Bs)[64])
{
    int tid = threadIdx.x;
    int ty = tid >> 4, tx = tid & 15;
    float acc[4][4];
#pragma unroll
    for (int i = 0; i < 4; i++)
#pragma unroll
        for (int j = 0; j < 4; j++) acc[i][j] = 0.f;

    for (int k0 = 0; k0 < K; k0 += 16) {
        {
            int m  = tid >> 2;
            int kk = (tid & 3) * 4;
            float4 v = *reinterpret_cast<const float4*>(&A[(size_t)(m0 + m) * K + k0 + kk]);
            As[kk + 0][m] = v.x; As[kk + 1][m] = v.y;
            As[kk + 2][m] = v.z; As[kk + 3][m] = v.w;
        }
        {
            int kk = tid >> 4;
            int c4 = (tid & 15) * 4;
            *reinterpret_cast<float4*>(&Bs[kk][c4]) =
                *reinterpret_cast<const float4*>(&Bm[(size_t)(k0 + kk) * N + n0 + c4]);
        }
        __syncthreads();
#pragma unroll
        for (int kk = 0; kk < 16; kk++) {
            float4 a4 = *reinterpret_cast<const float4*>(&As[kk][ty * 4]);
            float4 b4 = *reinterpret_cast<const float4*>(&Bs[kk][tx * 4]);
            float a[4] = {a4.x, a4.y, a4.z, a4.w};
            float b[4] = {b4.x, b4.y, b4.z, b4.w};
#pragma unroll
            for (int i = 0; i < 4; i++)
#pragma unroll
                for (int j = 0; j < 4; j++) acc[i][j] += a[i] * b[j];
        }
        __syncthreads();
    }
    float bx = 0.f, by = 0.f, bz = 0.f, bw = 0.f;
    if (bias) {
        bx = bias[n0 + tx * 4 + 0]; by = bias[n0 + tx * 4 + 1];
        bz = bias[n0 + tx * 4 + 2]; bw = bias[n0 + tx * 4 + 3];
    }
#pragma unroll
    for (int i = 0; i < 4; i++) {
        float4 o;
        o.x = acc[i][0] + bx; o.y = acc[i][1] + by;
        o.z = acc[i][2] + bz; o.w = acc[i][3] + bw;
        *reinterpret_cast<float4*>(&C[(size_t)(m0 + ty * 4 + i) * N + n0 + tx * 4]) = o;
    }
}

__global__ __launch_bounds__(256) void precompute_kernel(
    const float* __restrict__ inputs, const float* __restrict__ keys,
    const float* __restrict__ V, const float* __restrict__ W,
    const float* __restrict__ Ubias)
{
    __shared__ float As[16][64];
    __shared__ float Bs[16][64];
    int bx = blockIdx.x;
    if (bx < 32) {
        sgemm_tile_body(inputs, W, nullptr, g_Q,
                        (bx >> 3) * 64, (bx & 7) * 64, Ddim, Ddim, As, Bs);
    } else {
        int t = bx - 32;
        sgemm_tile_body(keys, V, Ubias, g_P,
                        0, t * 64, Ddim, Ddim, As, Bs);
    }
}

// ---------------- fused main kernel (tf32 3-split tensor cores) ----------------
// One CTA = 32 consecutive rows (one b, 32 j's) x all 512 cols.
// v = s + sigmoid(inputs.(s+key)) * relu(s@U + Q[b] + P[j]); out = (v>0) ? ||v_row|| : v.
__global__ __launch_bounds__(256, 2) void fused_kernel(
    const float* __restrict__ inputs,
    const float* __restrict__ state,
    const float* __restrict__ keys,
    const float* __restrict__ U,
    float* __restrict__ out)
{
    extern __shared__ float sm[];
    float* s_sm  = sm;                             // [32][SSTRIDE] row-major s tile
    float* Ubuf  = sm + 32 * SSTRIDE;              // 2 x [8][USTRIDE] U k-slabs
    float* inp   = Ubuf + 2 * 8 * USTRIDE;         // [512] inputs[b]
    float* qb    = inp + Ddim;                     // [512] Q[b]
    float* gate  = qb + Ddim;                      // [32]
    float* normv = gate + 32;                      // [32]
    float* red   = normv + 32;                     // [8][32]

    int tid  = threadIdx.x;
    int bx   = blockIdx.x;
    int row0 = bx * 32;
    int b    = bx >> 1;
    int j0   = (bx & 1) * 32;
    const float* srow = state + (size_t)row0 * Ddim;

    int lane = tid & 31;
    int w    = tid >> 5;
    int gid  = lane >> 2;        // 0..7
    int tig  = lane & 3;         // 0..3
    int cb   = w * 64;           // warp's column base

    // Prefetch U k-slabs 0 and 1 (each 8x512 floats) via cp.async
#pragma unroll
    for (int q = 0; q < 4; q++) {
        int c = tid + 256 * q;
        int kk = c >> 7, c4 = (c & 127) * 4;
        cp_async16(Ubuf + kk * USTRIDE + c4, U + (size_t)kk * Ddim + c4);
    }
    cp_commit();
#pragma unroll
    for (int q = 0; q < 4; q++) {
        int c = tid + 256 * q;
        int kk = c >> 7, c4 = (c & 127) * 4;
        cp_async16(Ubuf + 8 * USTRIDE + kk * USTRIDE + c4, U + (size_t)(8 + kk) * Ddim + c4);
    }
    cp_commit();

    // Stage inputs[b] and Q[b]
    if (tid < 128)
        reinterpret_cast<float4*>(inp)[tid] =
            reinterpret_cast<const float4*>(inputs + (size_t)b * Ddim)[tid];
    else
        reinterpret_cast<float4*>(qb)[tid - 128] =
            reinterpret_cast<const float4*>(g_Q + (size_t)b * Ddim)[tid - 128];

    // Stage s block, row-major with padded stride
#pragma unroll
    for (int q = 0; q < 16; q++) {
        int c = tid + 256 * q;
        int r = c >> 7;
        int f4 = c & 127;
        float4 v = reinterpret_cast<const float4*>(srow + (size_t)r * Ddim)[f4];
        *reinterpret_cast<float4*>(&s_sm[r * SSTRIDE + f4 * 4]) = v;
    }
    __syncthreads();

    // Gates: warp w handles rows w*4..w*4+3; arg = inputs.(s_j + key_j)
    {
#pragma unroll
        for (int i = 0; i < 4; i++) {
            int r = w * 4 + i;
            const float* kr = keys + (size_t)(j0 + r) * Ddim;
            const float* sr = s_sm + r * SSTRIDE;
            float z = 0.f;
            for (int k = lane; k < Ddim; k += 32)
                z += inp[k] * (sr[k] + kr[k]);
#pragma unroll
            for (int o = 16; o; o >>= 1) z += __shfl_xor_sync(0xffffffffu, z, o);
            if (lane == 0) gate[r] = 1.f / (1.f + expf(-z));
        }
    }

    // -------- tf32 split-3 MMA mainloop --------
    // warp tile: 32 rows x 64 cols -> 2 m16-frags x 8 n8-frags, 64 fp32 accums/thread
    float acc[2][8][4];
#pragma unroll
    for (int mi = 0; mi < 2; mi++)
#pragma unroll
        for (int nf = 0; nf < 8; nf++)
#pragma unroll
            for (int c = 0; c < 4; c++) acc[mi][nf][c] = 0.f;

#pragma unroll 1
    for (int s = 0; s < 64; s++) {
        if (s < 62) cp_wait1(); else cp_wait0();
        __syncthreads();
        const float* Ub = Ubuf + (s & 1) * (8 * USTRIDE);
        int k0 = s * 8;

        // A fragments (rows gid+mi*16 {+0,+8}, cols k0+tig {+0,+4}), split hi/lo
        unsigned ah[2][4], al[2][4];
#pragma unroll
        for (int mi = 0; mi < 2; mi++) {
            const float* Sb = s_sm + (gid + mi * 16) * SSTRIDE + k0 + tig;
            float f0 = Sb[0];
            float f1 = Sb[8 * SSTRIDE];
            float f2 = Sb[4];
            float f3 = Sb[8 * SSTRIDE + 4];
            split_tf32(f0, ah[mi][0], al[mi][0]);
            split_tf32(f1, ah[mi][1], al[mi][1]);
            split_tf32(f2, ah[mi][2], al[mi][2]);
            split_tf32(f3, ah[mi][3], al[mi][3]);
        }

#pragma unroll
        for (int nf = 0; nf < 8; nf++) {
            int col = cb + nf * 8 + gid;
            float g0 = Ub[tig * USTRIDE + col];
            float g1 = Ub[(tig + 4) * USTRIDE + col];
            unsigned bh[2], bl[2];
            split_tf32(g0, bh[0], bl[0]);
            split_tf32(g1, bh[1], bl[1]);
#pragma unroll
            for (int mi = 0; mi < 2; mi++) {
                mma_tf32(acc[mi][nf], ah[mi], bh);
                mma_tf32(acc[mi][nf], al[mi], bh);
                mma_tf32(acc[mi][nf], ah[mi], bl);
            }
        }
        __syncthreads();
        if (s + 2 < 64) {
            const float* Ug = U + (size_t)(s + 2) * 8 * Ddim;
            float* Ud = Ubuf + (s & 1) * (8 * USTRIDE);
#pragma unroll
            for (int q = 0; q < 4; q++) {
                int c = tid + 256 * q;
                int kk = c >> 7, c4 = (c & 127) * 4;
                cp_async16(Ud + kk * USTRIDE + c4, Ug + (size_t)kk * Ddim + c4);
            }
            cp_commit();
        }
    }

    // -------- epilogue: v = s + g*relu(acc + qb + P), row-norm partials --------
    float part[4];
#pragma unroll
    for (int mi = 0; mi < 2; mi++) {
#pragma unroll
        for (int h = 0; h < 2; h++) {
            int r = gid + mi * 16 + h * 8;
            float g = gate[r];
            const float* Pr = g_P + (size_t)(j0 + r) * Ddim;
            const float* Sr = s_sm + r * SSTRIDE;
            float psum = 0.f;
#pragma unroll
            for (int nf = 0; nf < 8; nf++) {
                int c0 = cb + nf * 8 + tig * 2;
                float2 p2 = *reinterpret_cast<const float2*>(Pr + c0);
                float2 s2 = *reinterpret_cast<const float2*>(Sr + c0);
                float pre0 = acc[mi][nf][h * 2 + 0] + qb[c0]     + p2.x;
                float pre1 = acc[mi][nf][h * 2 + 1] + qb[c0 + 1] + p2.y;
                float v0 = s2.x + g * fmaxf(pre0, 0.f);
                float v1 = s2.y + g * fmaxf(pre1, 0.f);
                acc[mi][nf][h * 2 + 0] = v0;
                acc[mi][nf][h * 2 + 1] = v1;
                psum += v0 * v0 + v1 * v1;
            }
            part[mi * 2 + h] = psum;
        }
    }
    // quad reduction over tig (4 lanes cover the row's 64 cols within this warp)
#pragma unroll
    for (int i = 0; i < 4; i++) {
        part[i] += __shfl_xor_sync(0xffffffffu, part[i], 1);
        part[i] += __shfl_xor_sync(0xffffffffu, part[i], 2);
    }
    if (tig == 0) {
#pragma unroll
        for (int mi = 0; mi < 2; mi++)
#pragma unroll
            for (int h = 0; h < 2; h++)
                red[w * 32 + gid + mi * 16 + h * 8] = part[mi * 2 + h];
    }
    __syncthreads();
    if (tid < 32) {
        float sum = 0.f;
#pragma unroll
        for (int ww = 0; ww < 8; ww++) sum += red[ww * 32 + tid];
        normv[tid] = fmaxf(sqrtf(sum), 1e-12f);
    }
    __syncthreads();

    // out = (v > 0) ? norm : v
#pragma unroll
    for (int mi = 0; mi < 2; mi++) {
#pragma unroll
        for (int h = 0; h < 2; h++) {
            int r = gid + mi * 16 + h * 8;
            float n = normv[r];
            float* orow = out + (size_t)(row0 + r) * Ddim;
#pragma unroll
            for (int nf = 0; nf < 8; nf++) {
                int c0 = cb + nf * 8 + tig * 2;
                float v0 = acc[mi][nf][h * 2 + 0];
                float v1 = acc[mi][nf][h * 2 + 1];
                float2 o;
                o.x = v0 > 0.f ? n : v0;
                o.y = v1 > 0.f ? n : v1;
                *reinterpret_cast<float2*>(orow + c0) = o;
            }
        }
    }
}

extern "C" void kernel_launch(void* const* d_in, const int* in_sizes, int n_in,
                              void* d_out, int out_size)
{
    const float* inputs = (const float*)d_in[0];
    const float* state  = (const float*)d_in[1];
    const float* keys   = (const float*)d_in[2];
    const float* U      = (const float*)d_in[3];
    const float* V      = (const float*)d_in[4];
    const float* W      = (const float*)d_in[5];
    const float* Ubias  = (const float*)d_in[6];
    float* out = (float*)d_out;
    (void)in_sizes; (void)n_in; (void)out_size;

    // Q = inputs@W (32 tiles) and P = keys@V + bias (8 tiles), one launch
    precompute_kernel<<<40, 256>>>(inputs, keys, V, W, Ubias);

    size_t smem = (size_t)(32 * SSTRIDE + 2 * 8 * USTRIDE + Ddim + Ddim + 32 + 32 + 8 * 32) * sizeof(float);
    cudaFuncSetAttribute(fused_kernel, cudaFuncAttributeMaxDynamicSharedMemorySize, (int)smem);
    fused_kernel<<<(Bdim * Jdim) / 32, 256, smem>>>(inputs, state, keys, U, out);
}